// round 5
// baseline (speedup 1.0000x reference)
#include <cuda_runtime.h>

#define NB 2
#define NC 64
#define D  64
#define NVOX (D*D*D)            // 262144
#define NCH  (NB*NC)            // 128
#define TOT  (NCH*NVOX)         // 33554432

#define FIX_T   0.02f
#define MAXFIX  (1<<22)

// Scratch (no cudaMalloc allowed)
__device__ float2 g_p [TOT];    // (qk, qkv) bit-exact proj output (fixup source)
__device__ float2 g_t1[TOT];    // after w pass
__device__ float2 g_t2[TOT];    // after h pass
__device__ int    g_cnt;
__device__ int    g_fixlist[MAXFIX];

__global__ void reset_kernel() { g_cnt = 0; }

// ---------------------------------------------------------------------------
// Stage 1 (fused): per-voxel projections + W-axis box sum.
//   Chains as two packed fma.rn.f32x2 streams (each lane IEEE fp32 FMA):
//     stream A: lanes (aq, ak), weights (wq,wk), operand (m,f)
//     stream B: lanes (0,  av), weights (0, wv), operand (m,f)
//   -> bit-identical to scalar sequential ascending-c chains (load-bearing
//   for near-zero-denominator voxels; see fixup).
//   Per-thread live state = mf[64] packed pairs only (no spill).
//   Block = 4 full w-rows; after each l, stage (qk,qkv) in a double-buffered
//   smem tile and emit the bounded 9-tap w-sum to g_t1 (replaces box_w).
// ---------------------------------------------------------------------------
__global__ __launch_bounds__(256) void proj_w_kernel(
    const float* __restrict__ mov, const float* __restrict__ fix,
    const float* __restrict__ qw,  const float* __restrict__ kw,
    const float* __restrict__ vw)
{
    extern __shared__ float2 sm2[];
    float2* swqk  = sm2;                 // [NC*NC] (wq,wk)   32 KB
    float2* swv2  = sm2 + NC*NC;         // [NC*NC] (0, wv)   32 KB
    float2* stile = sm2 + 2*NC*NC;       // [2][4][64] double-buffered tile 4 KB

    const int tid = threadIdx.x;
    for (int i = tid; i < NC*NC; i += 256) {
        swqk[i] = make_float2(qw[i], kw[i]);
        swv2[i] = make_float2(0.f, vw[i]);
    }
    __syncthreads();

    const int gid = blockIdx.x * 256 + tid;     // 0 .. NB*NVOX-1
    const int b   = (gid >= NVOX) ? 1 : 0;
    const int n   = gid - b * NVOX;
    const int w   = tid & 63;                   // n consecutive -> w = n & 63
    const int r   = tid >> 6;                   // row 0..3 within block

    const float* mp = mov + (long)b*NC*NVOX + n;
    const float* fp = fix + (long)b*NC*NVOX + n;

    unsigned long long mf[NC];   // packed (m[c], f[c])
    #pragma unroll
    for (int c = 0; c < NC; c++) {
        const float mv = mp[(long)c*NVOX];
        const float fv = fp[(long)c*NVOX];
        asm("mov.b64 %0, {%1,%2};" : "=l"(mf[c]) : "f"(mv), "f"(fv));
    }

    const long chan0 = (long)b*NC*NVOX + n;
    const int  lo = (w-4 < 0) ? 0 : w-4;
    const int  hi = (w+4 > D-1) ? D-1 : w+4;

    for (int l = 0; l < NC; l++) {
        const ulonglong2* wrow = (const ulonglong2*)(swqk + (l<<6));
        const ulonglong2* vrow = (const ulonglong2*)(swv2 + (l<<6));
        unsigned long long aqk = 0ull;   // lanes (aq, ak)
        unsigned long long avv = 0ull;   // lanes (0,  av)
        #pragma unroll
        for (int j = 0; j < NC/4; j++) {
            const ulonglong2 wa = wrow[2*j];
            const ulonglong2 wb = wrow[2*j+1];
            const ulonglong2 va = vrow[2*j];
            const ulonglong2 vb = vrow[2*j+1];
            asm("fma.rn.f32x2 %0, %1, %2, %0;" : "+l"(aqk) : "l"(wa.x), "l"(mf[4*j+0]));
            asm("fma.rn.f32x2 %0, %1, %2, %0;" : "+l"(avv) : "l"(va.x), "l"(mf[4*j+0]));
            asm("fma.rn.f32x2 %0, %1, %2, %0;" : "+l"(aqk) : "l"(wa.y), "l"(mf[4*j+1]));
            asm("fma.rn.f32x2 %0, %1, %2, %0;" : "+l"(avv) : "l"(va.y), "l"(mf[4*j+1]));
            asm("fma.rn.f32x2 %0, %1, %2, %0;" : "+l"(aqk) : "l"(wb.x), "l"(mf[4*j+2]));
            asm("fma.rn.f32x2 %0, %1, %2, %0;" : "+l"(avv) : "l"(vb.x), "l"(mf[4*j+2]));
            asm("fma.rn.f32x2 %0, %1, %2, %0;" : "+l"(aqk) : "l"(wb.y), "l"(mf[4*j+3]));
            asm("fma.rn.f32x2 %0, %1, %2, %0;" : "+l"(avv) : "l"(vb.y), "l"(mf[4*j+3]));
        }
        float aq, ak, zz, av;
        asm("mov.b64 {%0,%1}, %2;" : "=f"(aq), "=f"(ak) : "l"(aqk));
        asm("mov.b64 {%0,%1}, %2;" : "=f"(zz), "=f"(av) : "l"(avv));
        const float qk  = __fmul_rn(aq, ak);
        const float qkv = __fmul_rn(qk, av);
        const float2 pv = make_float2(qk, qkv);
        g_p[chan0 + (long)l*NVOX] = pv;

        // fused W-axis 9-tap bounded box sum (double-buffered tile)
        float2* tb = stile + ((l & 1) ? 4*D : 0) + r*D;
        tb[w] = pv;
        __syncthreads();
        float sx = 0.f, sy = 0.f;
        for (int j = lo; j <= hi; j++) { sx += tb[j].x; sy += tb[j].y; }
        g_t1[chan0 + (long)l*NVOX] = make_float2(sx, sy);
    }
}

// ---------------------------------------------------------------------------
// Stage 2b: fast box sum along H (float4 ring sliding window). g_t1 -> g_t2
// ---------------------------------------------------------------------------
__global__ __launch_bounds__(256) void box_h_kernel()
{
    const int t    = threadIdx.x;
    const int wp   = t & 31;
    const int z    = blockIdx.x * 8 + (t >> 5);   // gridDim.x = 8
    const int chan = blockIdx.y;
    const long base = ((long)chan*NVOX + (long)z*(D*D)) / 2 + wp;
    const float4* src = (const float4*)g_t1;
    float4*       dst = (float4*)g_t2;

    float4 ring[9];
    float4 s = make_float4(0.f, 0.f, 0.f, 0.f);
    #pragma unroll
    for (int j = 0; j < 4; j++) {
        float4 v = src[base + (long)j*(D/2)];
        ring[j % 9] = v;
        s.x += v.x; s.y += v.y; s.z += v.z; s.w += v.w;
    }
    #pragma unroll
    for (int i = 0; i < D; i++) {
        const int j = i + 4;
        if (j < D) {
            float4 v = src[base + (long)j*(D/2)];
            ring[j % 9] = v;
            s.x += v.x; s.y += v.y; s.z += v.z; s.w += v.w;
        }
        dst[base + (long)i*(D/2)] = s;
        const int j2 = i - 4;
        if (j2 >= 0) {
            float4 v = ring[j2 % 9];
            s.x -= v.x; s.y -= v.y; s.z -= v.z; s.w -= v.w;
        }
    }
}

// ---------------------------------------------------------------------------
// Stage 2c: fast box sum along Z + division; flag near-zero denominators.
// g_t2 -> out
// ---------------------------------------------------------------------------
__global__ __launch_bounds__(256) void box_z_div_kernel(float* __restrict__ out)
{
    const int t    = threadIdx.x;
    const int wp   = t & 31;
    const int h    = blockIdx.x * 8 + (t >> 5);   // gridDim.x = 8
    const int chan = blockIdx.y;
    const long ebase = (long)chan*NVOX + (long)h*D + 2*wp;
    const long base  = ebase >> 1;
    const float4* src = (const float4*)g_t2;
    float2*       o2  = (float2*)out;

    float4 ring[9];
    float4 s = make_float4(0.f, 0.f, 0.f, 0.f);
    #pragma unroll
    for (int j = 0; j < 4; j++) {
        float4 v = src[base + (long)j*(D*D/2)];
        ring[j % 9] = v;
        s.x += v.x; s.y += v.y; s.z += v.z; s.w += v.w;
    }
    #pragma unroll
    for (int i = 0; i < D; i++) {
        const int j = i + 4;
        if (j < D) {
            float4 v = src[base + (long)j*(D*D/2)];
            ring[j % 9] = v;
            s.x += v.x; s.y += v.y; s.z += v.z; s.w += v.w;
        }
        const long eidx = ebase + (long)i*(D*D);
        o2[eidx >> 1] = make_float2(__fdiv_rn(s.y, s.x), __fdiv_rn(s.w, s.z));
        if (fabsf(s.x) < FIX_T) {
            int slot = atomicAdd(&g_cnt, 1);
            if (slot < MAXFIX) g_fixlist[slot] = (int)eidx;
        }
        if (fabsf(s.z) < FIX_T) {
            int slot = atomicAdd(&g_cnt, 1);
            if (slot < MAXFIX) g_fixlist[slot] = (int)(eidx + 1);
        }
        const int j2 = i - 4;
        if (j2 >= 0) {
            float4 v = ring[j2 % 9];
            s.x -= v.x; s.y -= v.y; s.z -= v.z; s.w -= v.w;
        }
    }
}

// ---------------------------------------------------------------------------
// Stage 3: exact fixup — reference's sequential in-bounds 729-tap fold
// (ascending z,h,w; fp32 adds; init 0) over the bit-exact g_p field.
// ---------------------------------------------------------------------------
__global__ __launch_bounds__(256) void fixup_kernel(float* __restrict__ out)
{
    int cnt = g_cnt; if (cnt > MAXFIX) cnt = MAXFIX;
    for (int idx = blockIdx.x*256 + threadIdx.x; idx < cnt; idx += gridDim.x*256) {
        const int v    = g_fixlist[idx];
        const int chan = v >> 18;
        const int rem  = v & (NVOX-1);
        const int z = rem >> 12;
        const int h = (rem >> 6) & 63;
        const int w = rem & 63;
        const long cb = (long)chan*NVOX;

        const int zlo = z-4 < 0 ? 0 : z-4, zhi = z+4 > 63 ? 63 : z+4;
        const int hlo = h-4 < 0 ? 0 : h-4, hhi = h+4 > 63 ? 63 : h+4;
        const int wlo = w-4 < 0 ? 0 : w-4, whi = w+4 > 63 ? 63 : w+4;

        float sD = 0.f, sN = 0.f;
        for (int dz = zlo; dz <= zhi; dz++)
            for (int dh = hlo; dh <= hhi; dh++) {
                const float2* row = g_p + cb + ((long)dz*D + dh)*D;
                for (int dw = wlo; dw <= whi; dw++) {
                    float2 x = row[dw];
                    sD = __fadd_rn(sD, x.x);
                    sN = __fadd_rn(sN, x.y);
                }
            }
        out[v] = __fdiv_rn(sN, sD);
    }
}

extern "C" void kernel_launch(void* const* d_in, const int* in_sizes, int n_in,
                              void* d_out, int out_size) {
    (void)in_sizes; (void)n_in; (void)out_size;
    const float* mov = (const float*)d_in[0];
    const float* fix = (const float*)d_in[1];
    const float* qw  = (const float*)d_in[2];
    const float* kw  = (const float*)d_in[3];
    const float* vw  = (const float*)d_in[4];
    float* out = (float*)d_out;

    const int smem = (2*NC*NC + 2*4*D) * sizeof(float2);   // 69632 B
    cudaFuncSetAttribute(proj_w_kernel,
                         cudaFuncAttributeMaxDynamicSharedMemorySize, smem);

    reset_kernel<<<1, 1>>>();
    proj_w_kernel<<<(NB*NVOX)/256, 256, smem>>>(mov, fix, qw, kw, vw);
    box_h_kernel<<<dim3(8, NCH), 256>>>();
    box_z_div_kernel<<<dim3(8, NCH), 256>>>(out);
    fixup_kernel<<<512, 256>>>(out);
}